// round 14
// baseline (speedup 1.0000x reference)
#include <cuda_runtime.h>
#include <cuda_fp16.h>
#include <math.h>
#include <stdint.h>

// LLTM hybrid: tensor-core fp16x3 split GEMM (rows [0,3328)) running CONCURRENTLY
// (forked stream) with an exact fp32 SIMT GEMM (rows [3328,4096)) that harvests
// the otherwise-idle FMA pipe on the same SMs (co-resident small CTA).
// Both fuse the LLTM epilogue. Shapes: B=4096, F=2048, S=2048, K=4096, N=6144.

#define S_DIM 2048
#define B_DIM 4096
#define K_DIM 4096
#define N_DIM 6144
#define BK    32
#define NITER (K_DIM / BK)     // 128
#define STAGES 4

#define MT_ROWS 3328           // tensor rows (26 x 128)
#define MS_ROWS (B_DIM - MT_ROWS)  // 768 SIMT rows (12 x 64)

#define RSB      80
#define OFF_AH   0
#define OFF_AL   10240
#define OFF_BH   20480
#define OFF_BL   28160
#define STAGE_SZ 35840
#define SMEM_TOTAL (STAGES * STAGE_SZ)   // 143360

// ---------------- device scratch ----------------
__device__ __half g_Wh1[(size_t)N_DIM * K_DIM];
__device__ __half g_Wl2[(size_t)N_DIM * K_DIM];
__device__ __half g_Xh1[(size_t)B_DIM * K_DIM];
__device__ __half g_Xl2[(size_t)B_DIM * K_DIM];

// ---------------- helpers ----------------
__device__ __forceinline__ uint32_t smem_u32(const void* p) {
    uint32_t a;
    asm("{ .reg .u64 t; cvta.to.shared.u64 t, %1; cvt.u32.u64 %0, t; }" : "=r"(a) : "l"(p));
    return a;
}
__device__ __forceinline__ void cp_async16(uint32_t sdst, const void* gsrc) {
    asm volatile("cp.async.cg.shared.global [%0], [%1], 16;" :: "r"(sdst), "l"(gsrc) : "memory");
}
__device__ __forceinline__ void cp_commit() {
    asm volatile("cp.async.commit_group;" ::: "memory");
}
__device__ __forceinline__ void cp_wait2() {
    asm volatile("cp.async.wait_group 2;" ::: "memory");
}
__device__ __forceinline__ void cp_wait1() {
    asm volatile("cp.async.wait_group 1;" ::: "memory");
}
__device__ __forceinline__ void ldsm_x4(uint32_t& r0, uint32_t& r1, uint32_t& r2, uint32_t& r3,
                                        uint32_t addr) {
    asm volatile("ldmatrix.sync.aligned.m8n8.x4.shared.b16 {%0,%1,%2,%3}, [%4];"
                 : "=r"(r0), "=r"(r1), "=r"(r2), "=r"(r3) : "r"(addr));
}
__device__ __forceinline__ void mma16816(float* c, const uint32_t* a, uint32_t b0, uint32_t b1) {
    asm volatile("mma.sync.aligned.m16n8k16.row.col.f32.f16.f16.f32 "
                 "{%0,%1,%2,%3}, {%4,%5,%6,%7}, {%8,%9}, {%0,%1,%2,%3};"
                 : "+f"(c[0]), "+f"(c[1]), "+f"(c[2]), "+f"(c[3])
                 : "r"(a[0]), "r"(a[1]), "r"(a[2]), "r"(a[3]), "r"(b0), "r"(b1));
}
__device__ __forceinline__ void mma16816h(uint32_t* c, const uint32_t* a, uint32_t b0, uint32_t b1) {
    asm volatile("mma.sync.aligned.m16n8k16.row.col.f16.f16.f16.f16 "
                 "{%0,%1}, {%2,%3,%4,%5}, {%6,%7}, {%0,%1};"
                 : "+r"(c[0]), "+r"(c[1])
                 : "r"(a[0]), "r"(a[1]), "r"(a[2]), "r"(a[3]), "r"(b0), "r"(b1));
}

// ---------------- pre-pass: split X into fp16 hi/lo (tensor rows only needed, do all) ----------------
__global__ __launch_bounds__(256) void split_x_kernel(const float* __restrict__ input,
                                                      const float* __restrict__ old_h) {
    size_t idx = ((size_t)blockIdx.x * blockDim.x + threadIdx.x) * 4;
    int b = (int)(idx / K_DIM);
    int k = (int)(idx % K_DIM);
    const float* src = (k < S_DIM) ? old_h + (size_t)b * S_DIM + k
                                   : input + (size_t)b * (K_DIM - S_DIM) + (k - S_DIM);
    float4 v = *(const float4*)src;
    float vv[4] = {v.x, v.y, v.z, v.w};
    union { __half h[4]; uint2 u; } hi, lo;
    #pragma unroll
    for (int e = 0; e < 4; e++) {
        hi.h[e] = __float2half_rn(vv[e]);
        lo.h[e] = __float2half_rn(vv[e] - __half2float(hi.h[e]));
    }
    *(uint2*)&g_Xh1[idx] = hi.u;
    *(uint2*)&g_Xl2[idx] = lo.u;
}

// ---------------- pre-pass: transpose W[K,N] -> Wt[N,K] fp16 hi/lo ----------------
__global__ __launch_bounds__(256) void split_w_kernel(const float* __restrict__ W) {
    __shared__ float sh[32][33];
    int n0 = blockIdx.x * 32;
    int k0 = blockIdx.y * 32;
    int tx = threadIdx.x, ty = threadIdx.y;
    #pragma unroll
    for (int i = 0; i < 4; i++) {
        int k = k0 + ty + i * 8;
        sh[ty + i * 8][tx] = W[(size_t)k * N_DIM + n0 + tx];
    }
    __syncthreads();
    #pragma unroll
    for (int i = 0; i < 4; i++) {
        int nl = ty + i * 8;
        float v = sh[tx][nl];
        __half hi = __float2half_rn(v);
        __half lo = __float2half_rn(v - __half2float(hi));
        size_t off = (size_t)(n0 + nl) * K_DIM + k0 + tx;
        g_Wh1[off] = hi;
        g_Wl2[off] = lo;
    }
}

// ---------------- tensor-core fused GEMM + LLTM (rows [0, MT_ROWS)) ----------------
__global__ __launch_bounds__(256, 1) void lltm_mma_kernel(
    const float* __restrict__ bias,
    const float* __restrict__ old_c,
    float* __restrict__ out)
{
    extern __shared__ char smem[];
    const uint32_t sb = smem_u32(smem);

    const int tid  = threadIdx.x;
    const int wid  = tid >> 5;
    const int lane = tid & 31;
    const int m0 = blockIdx.x * 128;
    const int s0 = blockIdx.y * 32;

    uint32_t sm_off[7];
    const char* gp[7];
    #pragma unroll
    for (int i = 0; i < 7; i++) {
        int c = tid + i * 256;
        if (c < 1024) {
            int mat = c >> 9;
            int idx = c & 511;
            int r = idx >> 2, c16 = idx & 3;
            sm_off[i] = (mat ? OFF_AL : OFF_AH) + r * RSB + c16 * 16;
            const __half* base = mat ? g_Xl2 : g_Xh1;
            gp[i] = (const char*)(base + (size_t)(m0 + r) * K_DIM + c16 * 8);
        } else {
            int cc = c - 1024;
            int mat = cc / 384;
            int idx = cc % 384;
            int r = idx >> 2, c16 = idx & 3;
            int n = (r >> 5) * S_DIM + s0 + (r & 31);
            sm_off[i] = (mat ? OFF_BL : OFF_BH) + r * RSB + c16 * 16;
            const __half* base = mat ? g_Wl2 : g_Wh1;
            gp[i] = (const char*)(base + (size_t)n * K_DIM + c16 * 8);
        }
    }

    const uint32_t laneOff = (uint32_t)(((lane & 7) + ((lane >> 3) & 1) * 8) * RSB
                                        + (lane >> 4) * 16);
    const uint32_t aBase = sb + wid * (16 * RSB) + laneOff;
    const uint32_t bBase = sb + laneOff;

    float    accf[12][4];
    uint32_t accx[12][2];
    #pragma unroll
    for (int j = 0; j < 12; j++) {
        #pragma unroll
        for (int e = 0; e < 4; e++) accf[j][e] = 0.0f;
        accx[j][0] = 0u; accx[j][1] = 0u;
    }

    #pragma unroll
    for (int st = 0; st < STAGES - 1; st++) {
        #pragma unroll
        for (int i = 0; i < 7; i++)
            cp_async16(sb + st * STAGE_SZ + sm_off[i], gp[i] + (size_t)st * (BK * 2));
        cp_commit();
    }

    int rd = 0, wr = STAGES - 1;
    for (int kt = 0; kt < NITER; kt++) {
        cp_wait2();
        __syncthreads();

        if (kt + STAGES - 1 < NITER) {
            #pragma unroll
            for (int i = 0; i < 7; i++)
                cp_async16(sb + wr * STAGE_SZ + sm_off[i],
                           gp[i] + (size_t)(kt + STAGES - 1) * (BK * 2));
        }
        cp_commit();

        const uint32_t stg = (uint32_t)(rd * STAGE_SZ);
        #pragma unroll
        for (int kk = 0; kk < 2; kk++) {
            const uint32_t ko = kk * 32;
            uint32_t ah[4], al[4], bf[6][4];
            ldsm_x4(ah[0], ah[1], ah[2], ah[3], aBase + stg + OFF_AH + ko);
            ldsm_x4(al[0], al[1], al[2], al[3], aBase + stg + OFF_AL + ko);
            #pragma unroll
            for (int t = 0; t < 6; t++)
                ldsm_x4(bf[t][0], bf[t][1], bf[t][2], bf[t][3],
                        bBase + stg + OFF_BH + t * (16 * RSB) + ko);
            #pragma unroll
            for (int t = 0; t < 6; t++) {
                mma16816(accf[2 * t],     ah, bf[t][0], bf[t][2]);
                mma16816(accf[2 * t + 1], ah, bf[t][1], bf[t][3]);
            }
            #pragma unroll
            for (int t = 0; t < 6; t++) {
                mma16816h(accx[2 * t],     al, bf[t][0], bf[t][2]);
                mma16816h(accx[2 * t + 1], al, bf[t][1], bf[t][3]);
            }
            #pragma unroll
            for (int t = 0; t < 6; t++) {
                ldsm_x4(bf[t][0], bf[t][1], bf[t][2], bf[t][3],
                        bBase + stg + OFF_BL + t * (16 * RSB) + ko);
                mma16816h(accx[2 * t],     ah, bf[t][0], bf[t][2]);
                mma16816h(accx[2 * t + 1], ah, bf[t][1], bf[t][3]);
            }
        }
        rd = (rd + 1) & (STAGES - 1);
        wr = (wr + 1) & (STAGES - 1);
    }

    const int row0 = m0 + wid * 16 + (lane >> 2);
    const int scol = (lane & 3) * 2;
    const size_t BS = (size_t)B_DIM * S_DIM;

    #pragma unroll
    for (int j = 0; j < 4; j++) {
        const int sg = s0 + 8 * j + scol;
        const float b0a = __ldg(bias + sg);
        const float b0b = __ldg(bias + sg + 1);
        const float b1a = __ldg(bias + S_DIM + sg);
        const float b1b = __ldg(bias + S_DIM + sg + 1);
        const float b2a = __ldg(bias + 2 * S_DIM + sg);
        const float b2b = __ldg(bias + 2 * S_DIM + sg + 1);
        #pragma unroll
        for (int h = 0; h < 2; h++) {
            const int m = row0 + 8 * h;
            const size_t o = (size_t)m * S_DIM + sg;
            const float2 oc = *(const float2*)(old_c + o);
            const __half2 x0 = *(const __half2*)&accx[j][h];
            const __half2 x1 = *(const __half2*)&accx[j + 4][h];
            const __half2 x2 = *(const __half2*)&accx[j + 8][h];
            float nh[2], nc[2];
            #pragma unroll
            for (int e = 0; e < 2; e++) {
                float c0 = __half2float(e ? x0.y : x0.x);
                float c1 = __half2float(e ? x1.y : x1.x);
                float c2 = __half2float(e ? x2.y : x2.x);
                float g0 = accf[j][2 * h + e]     + c0 + (e ? b0b : b0a);
                float g1 = accf[j + 4][2 * h + e] + c1 + (e ? b1b : b1a);
                float g2 = accf[j + 8][2 * h + e] + c2 + (e ? b2b : b2a);
                float ig = 1.0f / (1.0f + __expf(-g0));
                float og = 1.0f / (1.0f + __expf(-g1));
                float cand = (g2 > 0.0f) ? g2 : expm1f(g2);
                float ncv = (e ? oc.y : oc.x) + cand * ig;
                nc[e] = ncv;
                nh[e] = tanhf(ncv) * og;
            }
            *(float2*)(out + o) = make_float2(nh[0], nh[1]);
            *(float2*)(out + BS + o) = make_float2(nc[0], nc[1]);
        }
    }
}

// ---------------- SIMT exact-fp32 fused GEMM + LLTM (rows [MT_ROWS, B)) ----------------
// CTA: 64m x 96n (gate-planar: 32 s x 3 gates), 128 threads, thread tile 8m x (2s x 3g).
// Small footprint (30KB smem, ~90 regs) so it CO-RESIDES with a tensor CTA and
// harvests the idle FMA pipe.
#define SBK 16
__global__ __launch_bounds__(128, 1) void lltm_simt_kernel(
    const float* __restrict__ W,
    const float* __restrict__ bias,
    const float* __restrict__ input,
    const float* __restrict__ old_h,
    const float* __restrict__ old_c,
    float* __restrict__ out)
{
    __shared__ float sA[3][64 * SBK];     // [m][k], 64B rows
    __shared__ float sB[3][SBK * 96];     // [k][j], j = g*32 + s_loc

    const int tid = threadIdx.x;
    const int tx = tid & 15;              // s-pair
    const int ty = tid >> 4;              // row group (0..7)
    const int m0 = MT_ROWS + blockIdx.y * 64;
    const int s0 = blockIdx.x * 32;

    const uint32_t sbA = smem_u32(&sA[0][0]);
    const uint32_t sbB = smem_u32(&sB[0][0]);

    // A chunks: 2 per thread. c = tid*2+i: r=c>>2, q=c&3 -> 16B at row r, k-off 4q
    int aR[2], aQ[2];
    // B chunks: 3 per thread. c = tid*3+i: k=c/24, q=c%24: g=q>>3, o=(q&7)*4
    int bK[3]; uint32_t bSm[3]; size_t bCol[3];
    uint32_t aSm[2];
    #pragma unroll
    for (int i = 0; i < 2; i++) {
        int c = tid * 2 + i;
        aR[i] = c >> 2; aQ[i] = (c & 3) * 4;
        aSm[i] = (uint32_t)(aR[i] * SBK + aQ[i]) * 4;
    }
    #pragma unroll
    for (int i = 0; i < 3; i++) {
        int c = tid * 3 + i;
        bK[i] = c / 24;
        int q = c % 24;
        int g = q >> 3, o = (q & 7) * 4;
        bSm[i] = (uint32_t)(bK[i] * 96 + g * 32 + o) * 4;
        bCol[i] = (size_t)g * S_DIM + s0 + o;
    }

    float acc[8][6];
    #pragma unroll
    for (int i = 0; i < 8; i++)
        #pragma unroll
        for (int j = 0; j < 6; j++) acc[i][j] = 0.0f;

    const int NKT = K_DIM / SBK;   // 256

    // issue stage st for k-tile ktg
    #define SIMT_ISSUE(st, ktg) do {                                                  \
        int kg = (ktg) * SBK;                                                         \
        _Pragma("unroll")                                                             \
        for (int i = 0; i < 2; i++) {                                                 \
            int k = kg + aQ[i];                                                       \
            const float* src = (k < S_DIM)                                            \
                ? old_h + (size_t)(m0 + aR[i]) * S_DIM + k                            \
                : input + (size_t)(m0 + aR[i]) * (K_DIM - S_DIM) + (k - S_DIM);       \
            cp_async16(sbA + (st) * (64 * SBK * 4) + aSm[i], src);                    \
        }                                                                             \
        _Pragma("unroll")                                                             \
        for (int i = 0; i < 3; i++) {                                                 \
            const float* src = W + (size_t)(kg + bK[i]) * N_DIM + bCol[i];            \
            cp_async16(sbB + (st) * (SBK * 96 * 4) + bSm[i], src);                    \
        }                                                                             \
        cp_commit();                                                                  \
    } while (0)

    SIMT_ISSUE(0, 0);
    SIMT_ISSUE(1, 1);

    int st = 0;
    for (int kt = 0; kt < NKT; kt++) {
        cp_wait1();
        __syncthreads();
        if (kt + 2 < NKT) {
            int wst = st + 2; if (wst >= 3) wst -= 3;
            SIMT_ISSUE(wst, kt + 2);
        } else {
            cp_commit();   // keep group count uniform
        }
        const float* A = sA[st];
        const float* Bt = sB[st];
        #pragma unroll
        for (int k = 0; k < SBK; k++) {
            float rM[8], rN[6];
            #pragma unroll
            for (int i = 0; i < 8; i++) rM[i] = A[(ty * 8 + i) * SBK + k];
            #pragma unroll
            for (int g = 0; g < 3; g++) {
                float2 v = *(const float2*)&Bt[k * 96 + g * 32 + 2 * tx];
                rN[2 * g] = v.x; rN[2 * g + 1] = v.y;
            }
            #pragma unroll
            for (int i = 0; i < 8; i++)
                #pragma unroll
                for (int j = 0; j < 6; j++)
                    acc[i][j] = fmaf(rM[i], rN[j], acc[i][j]);
        }
        __syncthreads();
        if (++st == 3) st = 0;
    }

    // fused epilogue
    const int sg = s0 + 2 * tx;
    const size_t BS = (size_t)B_DIM * S_DIM;
    const float b0a = bias[sg],             b0b = bias[sg + 1];
    const float b1a = bias[S_DIM + sg],     b1b = bias[S_DIM + sg + 1];
    const float b2a = bias[2 * S_DIM + sg], b2b = bias[2 * S_DIM + sg + 1];
    #pragma unroll
    for (int i = 0; i < 8; i++) {
        const int m = m0 + ty * 8 + i;
        const size_t o = (size_t)m * S_DIM + sg;
        const float2 oc = *(const float2*)(old_c + o);
        float nh[2], nc[2];
        #pragma unroll
        for (int e = 0; e < 2; e++) {
            float g0 = acc[i][0 + e] + (e ? b0b : b0a);
            float g1 = acc[i][2 + e] + (e ? b1b : b1a);
            float g2 = acc[i][4 + e] + (e ? b2b : b2a);
            float ig = 1.0f / (1.0f + __expf(-g0));
            float og = 1.0f / (1.0f + __expf(-g1));
            float cand = (g2 > 0.0f) ? g2 : expm1f(g2);
            float ncv = (e ? oc.y : oc.x) + cand * ig;
            nc[e] = ncv;
            nh[e] = tanhf(ncv) * og;
        }
        *(float2*)(out + o) = make_float2(nh[0], nh[1]);
        *(float2*)(out + BS + o) = make_float2(nc[0], nc[1]);
    }
}

// ---------------- launch: fork-join so SIMT overlaps the tensor kernel ----------------
extern "C" void kernel_launch(void* const* d_in, const int* in_sizes, int n_in,
                              void* d_out, int out_size) {
    const float* W     = (const float*)d_in[0];
    const float* bias  = (const float*)d_in[1];
    const float* input = (const float*)d_in[2];
    const float* old_h = (const float*)d_in[3];
    const float* old_c = (const float*)d_in[4];
    float* out = (float*)d_out;

    static cudaStream_t s2 = nullptr;
    static cudaEvent_t evFork = nullptr, evJoin = nullptr;
    static bool attrs_set = false;
    if (!s2) {
        cudaStreamCreateWithFlags(&s2, cudaStreamNonBlocking);
        cudaEventCreateWithFlags(&evFork, cudaEventDisableTiming);
        cudaEventCreateWithFlags(&evJoin, cudaEventDisableTiming);
    }
    if (!attrs_set) {
        cudaFuncSetAttribute(lltm_mma_kernel, cudaFuncAttributeMaxDynamicSharedMemorySize, SMEM_TOTAL);
        cudaFuncSetAttribute(lltm_simt_kernel, cudaFuncAttributePreferredSharedMemoryCarveout, 100);
        attrs_set = true;
    }

    // fork: SIMT branch (independent of pre-passes, reads raw fp32 inputs)
    cudaEventRecord(evFork, 0);
    cudaStreamWaitEvent(s2, evFork, 0);
    {
        dim3 gs(S_DIM / 32, MS_ROWS / 64);   // (64, 12)
        lltm_simt_kernel<<<gs, 128, 0, s2>>>(W, bias, input, old_h, old_c, out);
    }

    // main branch: pre-pass splits + tensor kernel
    {
        size_t nthreads = (size_t)B_DIM * K_DIM / 4;
        split_x_kernel<<<(int)(nthreads / 256), 256>>>(input, old_h);
        dim3 g(N_DIM / 32, K_DIM / 32);
        split_w_kernel<<<g, dim3(32, 8)>>>(W);
        dim3 grid(MT_ROWS / 128, S_DIM / 32);   // (26, 64)
        lltm_mma_kernel<<<grid, 256, SMEM_TOTAL>>>(bias, old_c, out);
    }

    // join
    cudaEventRecord(evJoin, s2);
    cudaStreamWaitEvent(0, evJoin, 0);
}